// round 11
// baseline (speedup 1.0000x reference)
#include <cuda_runtime.h>
#include <cuda_bf16.h>
#include <cstdint>

// Resample2d bilinear warp — smem-staged gather with cp.async depth-3 pipeline.
// input1: [8,64,384,512] f32, input2(flow): [8,2,384,512] f32, out NCHW f32.
//
// Model (R2-R9): binder = l1tex wavefront queue (~1 wf/cyc/SM). Direct gather
// (213us) = ~19 wf/warp-channel (4 divergent LDG.32 x ~4.7 wf + store).
// R5 staging failed on LATENCY (depth-1 buffer -> DRAM latency exposed per
// barrier phase), not on work (DRAM counters showed L2 absorbed the halo
// overfetch). This version: 8h x 32w block, per channel stage a 15x38 halo
// tile with cp.async.ca 4B copies (no register round-trip), 4 buffers /
// depth-3 groups, ONE __syncthreads per channel (issue into the buffer freed
// by the previous barrier). Gather = 4 LDS (stride 39, sparse conflicts) +
// coalesced STG. ~11-12 wf/warp-channel. Lanes outside the tile (~0.5%) use
// the identical global-LDG path; staged content is border-clamped so smem
// values equal the exact global values.

#define B_ 8
#define D_ 64
#define H_ 384
#define W_ 512
#define PLANE_ (H_ * W_)
#define TPB 256
#define BH 8
#define BW 32
#define MG 3                 // halo margin
#define NR 15                // staged rows  (BH + 2*MG + 1)
#define NC 38                // staged cols  (BW + 2*MG)
#define SSTR 39              // padded smem row stride (bank shift 7/row)
#define TSZ (NR * SSTR)      // 585 floats per stage
#define NCPY (NR * NC)       // 570 copy elements

__device__ __forceinline__ unsigned smem_u32(const void* p) {
    unsigned a;
    asm("{ .reg .u64 t; cvta.to.shared.u64 t, %1; cvt.u32.u64 %0, t; }"
        : "=r"(a) : "l"(p));
    return a;
}
#define CP4(dst_u32, src_ptr) \
    asm volatile("cp.async.ca.shared.global [%0], [%1], 4;" \
                 :: "r"(dst_u32), "l"(src_ptr))
#define CP_COMMIT() asm volatile("cp.async.commit_group;" ::: "memory")
#define CP_WAIT2()  asm volatile("cp.async.wait_group 2;" ::: "memory")

__global__ __launch_bounds__(TPB)
void resample2d_kernel(const float* __restrict__ img,
                       const float* __restrict__ flow,
                       float* __restrict__ out)
{
    __shared__ float tile[4][TSZ];

    const int tid = threadIdx.x;
    int gx = blockIdx.x;
    const int wb = gx & 15;              // W/BW = 16
    gx >>= 4;
    const int hb = gx % (H_ / BH);       // 48
    const int b  = gx / (H_ / BH);
    const int h0 = hb * BH;
    const int w0 = wb * BW;
    const int h = h0 + (tid >> 5);       // warp k -> output row h0+k
    const int w = w0 + (tid & 31);

    // ---- flow / weights / indices (once per thread) ----
    const unsigned foff = (unsigned)b * (2u * PLANE_) + (unsigned)h * W_ + w;
    const float u = __ldg(flow + foff);
    const float v = __ldg(flow + foff + PLANE_);

    float fx = (float)w + u;
    float fy = (float)h + v;
    fx = fminf(fmaxf(fx, 0.0f), (float)(W_ - 1));
    fy = fminf(fmaxf(fy, 0.0f), (float)(H_ - 1));
    const int x0 = min((int)fx, W_ - 2);
    const int y0 = min((int)fy, H_ - 2);
    const float wx = fx - (float)x0;
    const float wy = fy - (float)y0;

    const float w00 = (1.0f - wy) * (1.0f - wx);
    const float w01 = (1.0f - wy) * wx;
    const float w10 = wy * (1.0f - wx);
    const float w11 = wy * wx;

    // ---- tile-local gather coords ----
    const int tr = y0 - (h0 - MG);
    const int tc = x0 - (w0 - MG);
    const bool ok = (tr >= 0) & (tr <= NR - 2) & (tc >= 0) & (tc <= NC - 2);
    const int sb = tr * SSTR + tc;

    // ---- staging slots (loop-invariant): <=3 copies per thread ----
    const float* pbase = img + (size_t)b * (D_ * PLANE_);
    unsigned gso0, gso1, gso2 = 0, sso0, sso1, sso2 = 0;
    bool has2;
    {
        int idx = tid;
        int r = idx / NC, c = idx - r * NC;
        int gy = min(max(h0 - MG + r, 0), H_ - 1);
        int gc = min(max(w0 - MG + c, 0), W_ - 1);
        gso0 = (unsigned)(gy * W_ + gc);
        sso0 = (unsigned)(r * SSTR + c) * 4u;

        idx = tid + TPB;
        r = idx / NC; c = idx - r * NC;
        gy = min(max(h0 - MG + r, 0), H_ - 1);
        gc = min(max(w0 - MG + c, 0), W_ - 1);
        gso1 = (unsigned)(gy * W_ + gc);
        sso1 = (unsigned)(r * SSTR + c) * 4u;

        idx = tid + 2 * TPB;
        has2 = (idx < NCPY);
        if (has2) {
            r = idx / NC; c = idx - r * NC;
            gy = min(max(h0 - MG + r, 0), H_ - 1);
            gc = min(max(w0 - MG + c, 0), W_ - 1);
            gso2 = (unsigned)(gy * W_ + gc);
            sso2 = (unsigned)(r * SSTR + c) * 4u;
        }
    }
    const unsigned smb = smem_u32(&tile[0][0]);

    // fallback global base + output base
    const float* gp = pbase + (unsigned)y0 * W_ + (unsigned)x0;
    float* po = out + (size_t)b * (D_ * PLANE_) + (unsigned)h * W_ + (unsigned)w;

    // ---- prologue: issue channels 0..2 into buffers 0..2 ----
    #pragma unroll
    for (int d = 0; d < 3; ++d) {
        const unsigned sbuf = smb + (unsigned)(d * TSZ) * 4u;
        const float* src = pbase + (size_t)d * PLANE_;
        CP4(sbuf + sso0, src + gso0);
        CP4(sbuf + sso1, src + gso1);
        if (has2) CP4(sbuf + sso2, src + gso2);
        CP_COMMIT();
    }

    // ---- main loop: one barrier per channel ----
    for (int d = 0; d < D_; ++d) {
        CP_WAIT2();              // own group for channel d complete
        __syncthreads();         // publish smem; also frees buffer (d-1)&3

        // issue channel d+3 into buffer (d+3)&3 (== (d-1)&3, just freed)
        if (d + 3 < D_) {
            const int dn = d + 3;
            const unsigned sbuf = smb + (unsigned)((dn & 3) * TSZ) * 4u;
            const float* src = pbase + (size_t)dn * PLANE_;
            CP4(sbuf + sso0, src + gso0);
            CP4(sbuf + sso1, src + gso1);
            if (has2) CP4(sbuf + sso2, src + gso2);
        }
        CP_COMMIT();             // commit every iter (keeps wait_group ordering)

        // gather + blend for channel d
        float a00, a01, a10, a11;
        if (ok) {
            const float* tb = &tile[d & 3][0];
            a00 = tb[sb];
            a01 = tb[sb + 1];
            a10 = tb[sb + SSTR];
            a11 = tb[sb + SSTR + 1];
        } else {
            const float* g = gp + (size_t)d * PLANE_;
            a00 = __ldg(g);
            a01 = __ldg(g + 1);
            a10 = __ldg(g + W_);
            a11 = __ldg(g + W_ + 1);
        }
        float r = w00 * a00;
        r = fmaf(w01, a01, r);
        r = fmaf(w10, a10, r);
        r = fmaf(w11, a11, r);
        po[(size_t)d * PLANE_] = r;
    }
}

extern "C" void kernel_launch(void* const* d_in, const int* in_sizes, int n_in,
                              void* d_out, int out_size)
{
    const float* img  = (const float*)d_in[0];
    const float* flow = (const float*)d_in[1];
    float* out = (float*)d_out;

    dim3 grid((W_ / BW) * (H_ / BH) * B_);   // 16 * 48 * 8 = 6144
    dim3 block(TPB);
    resample2d_kernel<<<grid, block>>>(img, flow, out);
}

// round 12
// speedup vs baseline: 1.3435x; 1.3435x over previous
#include <cuda_runtime.h>
#include <cuda_bf16.h>
#include <cstdint>

// Resample2d bilinear warp — smem-staged gather, 16B cp.async depth-3 pipeline.
// input1: [8,64,384,512] f32, input2(flow): [8,2,384,512] f32, out NCHW f32.
//
// R11 (scalar cp.async) lost to LDGSTS issue cost: rt = 8 cyc/op SIZE-
// INDEPENDENT, and 570 4B ops/block-channel = ~18 cyc/warp-channel. Fix:
// 16B cp.async -> 165 ops/block-channel (15 rows x 11). Tile cols NC=44,
// xlo = clamp(w0-4, 0, W-44) (always mult of 4 -> 16B-aligned global src;
// SSTR=44 -> 16B-aligned smem dst). Rows border-clamped per-row; content of
// tile row tr equals global row y0 exactly whenever the 'ok' test passes, so
// arithmetic is bit-identical to the direct kernel. Out-of-tile lanes
// (~0.5%) take the identical global-LDG path. Depth-3 pipeline, 4 buffers,
// one __syncthreads per channel (R11 structure, proven latency-sound).

#define B_ 8
#define D_ 64
#define H_ 384
#define W_ 512
#define PLANE_ (H_ * W_)
#define TPB 256
#define BH 8
#define BW 32
#define MGY 3                // row margin
#define NR 15                // staged rows (BH + 2*MGY + 1)
#define NC 44                // staged cols (mult of 4)
#define NC16 (NC / 4)        // 11 16B ops per row
#define SSTR NC              // smem row stride in floats (16B aligned)
#define TSZ (NR * SSTR)      // 660 floats
#define NOPS (NR * NC16)     // 165 16B copies per channel

__device__ __forceinline__ unsigned smem_u32(const void* p) {
    unsigned a;
    asm("{ .reg .u64 t; cvta.to.shared.u64 t, %1; cvt.u32.u64 %0, t; }"
        : "=r"(a) : "l"(p));
    return a;
}
#define CP16(dst_u32, src_ptr) \
    asm volatile("cp.async.cg.shared.global [%0], [%1], 16;" \
                 :: "r"(dst_u32), "l"(src_ptr))
#define CP_COMMIT() asm volatile("cp.async.commit_group;" ::: "memory")
#define CP_WAIT2()  asm volatile("cp.async.wait_group 2;" ::: "memory")

__global__ __launch_bounds__(TPB)
void resample2d_kernel(const float* __restrict__ img,
                       const float* __restrict__ flow,
                       float* __restrict__ out)
{
    __shared__ float tile[4][TSZ];

    const int tid = threadIdx.x;
    int gx = blockIdx.x;
    const int wb = gx & 15;              // W/BW = 16
    gx >>= 4;
    const int hb = gx % (H_ / BH);       // 48
    const int b  = gx / (H_ / BH);
    const int h0 = hb * BH;
    const int w0 = wb * BW;
    const int h = h0 + (tid >> 5);       // warp k -> output row h0+k
    const int w = w0 + (tid & 31);

    // ---- flow / weights / indices ----
    const unsigned foff = (unsigned)b * (2u * PLANE_) + (unsigned)h * W_ + w;
    const float u = __ldg(flow + foff);
    const float v = __ldg(flow + foff + PLANE_);

    float fx = (float)w + u;
    float fy = (float)h + v;
    fx = fminf(fmaxf(fx, 0.0f), (float)(W_ - 1));
    fy = fminf(fmaxf(fy, 0.0f), (float)(H_ - 1));
    const int x0 = min((int)fx, W_ - 2);
    const int y0 = min((int)fy, H_ - 2);
    const float wx = fx - (float)x0;
    const float wy = fy - (float)y0;

    const float w00 = (1.0f - wy) * (1.0f - wx);
    const float w01 = (1.0f - wy) * wx;
    const float w10 = wy * (1.0f - wx);
    const float w11 = wy * wx;

    // ---- tile geometry ----
    const int ylo = h0 - MGY;                        // content rows clamped
    int xlo = w0 - 4;
    xlo = max(0, min(xlo, W_ - NC));                 // mult of 4 always

    const int tr = y0 - ylo;
    const int tc = x0 - xlo;
    const bool ok = (tr >= 0) & (tr <= NR - 2) & (tc >= 0) & (tc <= NC - 2);
    const int sb = tr * SSTR + tc;

    // ---- one 16B staging slot per thread (tid < NOPS) ----
    const float* pbase = img + (size_t)b * (D_ * PLANE_);
    const bool cpy = (tid < NOPS);
    unsigned gso = 0, sso = 0;
    if (cpy) {
        const int r = tid / NC16;
        const int c16 = tid - r * NC16;
        const int gy = min(max(ylo + r, 0), H_ - 1);
        gso = (unsigned)(gy * W_ + xlo + c16 * 4);
        sso = (unsigned)(r * SSTR + c16 * 4) * 4u;
    }
    const unsigned smb = smem_u32(&tile[0][0]);

    const float* gp = pbase + (unsigned)y0 * W_ + (unsigned)x0;   // fallback
    float* po = out + (size_t)b * (D_ * PLANE_) + (unsigned)h * W_ + (unsigned)w;

    // ---- prologue: channels 0..2 into buffers 0..2 ----
    #pragma unroll
    for (int d = 0; d < 3; ++d) {
        if (cpy) {
            CP16(smb + (unsigned)(d * TSZ) * 4u + sso,
                 pbase + (size_t)d * PLANE_ + gso);
        }
        CP_COMMIT();
    }

    // ---- main loop: one barrier per channel ----
    for (int d = 0; d < D_; ++d) {
        CP_WAIT2();              // group for channel d complete
        __syncthreads();         // publish smem; frees buffer (d-1)&3

        if (d + 3 < D_ && cpy) { // refill the just-freed buffer
            const int dn = d + 3;
            CP16(smb + (unsigned)((dn & 3) * TSZ) * 4u + sso,
                 pbase + (size_t)dn * PLANE_ + gso);
        }
        CP_COMMIT();

        float a00, a01, a10, a11;
        if (ok) {
            const float* tb = &tile[d & 3][0];
            a00 = tb[sb];
            a01 = tb[sb + 1];
            a10 = tb[sb + SSTR];
            a11 = tb[sb + SSTR + 1];
        } else {
            const float* g = gp + (size_t)d * PLANE_;
            a00 = __ldg(g);
            a01 = __ldg(g + 1);
            a10 = __ldg(g + W_);
            a11 = __ldg(g + W_ + 1);
        }
        float r = w00 * a00;
        r = fmaf(w01, a01, r);
        r = fmaf(w10, a10, r);
        r = fmaf(w11, a11, r);
        po[(size_t)d * PLANE_] = r;
    }
}

extern "C" void kernel_launch(void* const* d_in, const int* in_sizes, int n_in,
                              void* d_out, int out_size)
{
    const float* img  = (const float*)d_in[0];
    const float* flow = (const float*)d_in[1];
    float* out = (float*)d_out;

    dim3 grid((W_ / BW) * (H_ / BH) * B_);   // 16 * 48 * 8 = 6144
    dim3 block(TPB);
    resample2d_kernel<<<grid, block>>>(img, flow, out);
}